// round 17
// baseline (speedup 1.0000x reference)
#include <cuda_runtime.h>
#include <cuda_bf16.h>
#include <math.h>
#include <cstdint>

#define NN 100000
#define NR 8
#define NE 400000
#define DD 128
#define NL 3

#define SNB 1563                 // scan blocks: ceil(800000/512)
#define FILLB 1563               // fill blocks per relation: ceil(NE/256)

// ---------------- device scratch (static, no allocations) ----------------
__device__ float         g_bufA[NN * DD];
__device__ float         g_bufB[NN * DD];
__device__ float         g_el[NR * NN];
__device__ float         g_er[NR * NN];
__device__ float         g_vl[NL * NR * DD];
__device__ float         g_vr[NL * NR * DD];
__device__ __nv_bfloat16 g_whi[(size_t)NL * NR * DD * DD];
__device__ __nv_bfloat16 g_wlo[(size_t)NL * NR * DD * DD];
__device__ __nv_bfloat16 g_yhi[(size_t)NR * NN * DD];
__device__ __nv_bfloat16 g_ylo[(size_t)NR * NN * DD];
__device__ int           g_cnt[NR * NN];       // zero at start; reset by scan
__device__ int           g_fill[NR * NN];      // reset by scan
__device__ int           g_rowptrF[NR * NN + 1];
__device__ int           g_csrc[(size_t)NR * NE];
__device__ int           g_cdst[(size_t)NR * NE];
__device__ uint2         g_ws[(size_t)NR * NE];   // (w, src) per CSR slot
__device__ int           g_state[SNB];         // lookback: (value<<2)|flag
__device__ int           g_ticket;

// =================== kernel 1: hist + scan-state reset =====================
__global__ void hist_kernel(const int* __restrict__ edst) {
    int b = blockIdx.x;
    int tid = threadIdx.x;
    if (b < NR * FILLB) {
        int r = b / FILLB;
        int i = (b % FILLB) * 256 + tid;
        if (i < NE) {
            int d = edst[(size_t)r * NE + i];
            atomicAdd(&g_cnt[r * NN + d], 1);
        }
    } else {
        int i = (b - NR * FILLB) * 256 + tid;
        if (i < SNB) g_state[i] = 0;
        if (i == 0) g_ticket = 0;
    }
}

// =================== kernel 2: lookback scan + W prep + vecs ===============
__global__ void __launch_bounds__(512)
scan_prep_kernel(const float* __restrict__ fsw,
                 const float* __restrict__ fdw,
                 const float* __restrict__ al,
                 const float* __restrict__ ar) {
    int b = blockIdx.x;
    int tid = threadIdx.x;
    if (b < SNB) {
        __shared__ int sh[512];
        __shared__ int sbc[2];
        if (tid == 0) sbc[0] = atomicAdd(&g_ticket, 1);
        __syncthreads();
        int vid = sbc[0];
        int e = vid * 512 + tid;
        int v = 0;
        if (e < NR * NN) {
            v = g_cnt[e];
            g_cnt[e] = 0;
            g_fill[e] = 0;
        }
        sh[tid] = v;
        __syncthreads();
#pragma unroll
        for (int off = 1; off < 512; off <<= 1) {
            int t = (tid >= off) ? sh[tid - off] : 0;
            __syncthreads();
            sh[tid] += t;
            __syncthreads();
        }
        int incl = sh[tid];
        int btot = sh[511];
        if (tid == 0) {
            atomicExch(&g_state[vid], (btot << 2) | 1);
            int run = 0;
            int p = vid - 1;
            while (p >= 0) {
                int w = atomicAdd(&g_state[p], 0);
                int f = w & 3;
                if (f == 0) continue;
                run += (w >> 2);
                if (f == 2) break;
                p--;
            }
            atomicExch(&g_state[vid], ((run + btot) << 2) | 2);
            sbc[1] = run;
            if (vid == SNB - 1) {
                g_rowptrF[NR * NN] = run + btot;
                g_ticket = 0;
            }
        }
        __syncthreads();
        int run = sbc[1];
        if (e < NR * NN) g_rowptrF[e] = run + incl - v;
    } else if (b < SNB + 768) {
        int i = (b - SNB) * 512 + tid;
        float v = fsw[i];
        __nv_bfloat16 hi = __float2bfloat16_rn(v);
        g_whi[i] = hi;
        g_wlo[i] = __float2bfloat16_rn(v - __bfloat162float(hi));
    } else if (tid < 128) {
        int bb = b - SNB - 768;       // 0..47
        int l = bb >> 4;
        int sub = bb & 15;
        int r = sub >> 1;
        size_t wo = ((size_t)l * NR + r) * DD * DD;
        const float* W = (sub & 1) ? (fdw + wo) : (fsw + wo);
        const float* a = ((sub & 1) ? ar : al) + (l * NR + r) * DD;
        int k = tid;
        float s = 0.f;
#pragma unroll 8
        for (int j = 0; j < DD; j++) s += a[j] * W[j * DD + k];
        float* o = (sub & 1) ? g_vr : g_vl;
        o[(l * NR + r) * DD + k] = s;
    }
}

// -------- scores block body (256 threads) ----------------------------------
__device__ __forceinline__ void scores_block(const float* __restrict__ x,
                                             const float* __restrict__ vl,
                                             const float* __restrict__ vr,
                                             int n0) {
    __shared__ float xs[32][133];
    __shared__ float vv[16][DD];
    int tid = threadIdx.x;
    for (int i = tid; i < 16 * DD; i += 256) {
        int v = i >> 7, k = i & 127;
        vv[v][k] = (v < 8) ? vl[v * DD + k] : vr[(v - 8) * DD + k];
    }
    for (int i = tid; i < 32 * DD; i += 256) {
        int r = i >> 7, k = i & 127;
        xs[r][k] = x[(size_t)(n0 + r) * DD + k];
    }
    __syncthreads();

    int node = tid & 31;
    int v0 = (tid >> 5) * 2;
    float a0 = 0.f, a1 = 0.f;
#pragma unroll 8
    for (int k = 0; k < DD; k++) {
        float xv = xs[node][k];
        a0 += xv * vv[v0][k];
        a1 += xv * vv[v0 + 1][k];
    }
    int n = n0 + node;
    if (v0 < 8) g_el[v0 * NN + n] = a0;
    else        g_er[(v0 - 8) * NN + n] = a0;
    int v1 = v0 + 1;
    if (v1 < 8) g_el[v1 * NN + n] = a1;
    else        g_er[(v1 - 8) * NN + n] = a1;
}

// =================== kernel 3: CSR fill (+cdst) + layer-0 scores ===========
__global__ void __launch_bounds__(256)
fill_scores_kernel(const int* __restrict__ esrc,
                   const int* __restrict__ edst,
                   const float* __restrict__ x,
                   const float* __restrict__ vl0,
                   const float* __restrict__ vr0) {
    int b = blockIdx.x;
    if (b < NR * FILLB) {
        int r = b / FILLB;
        int i = (b % FILLB) * 256 + threadIdx.x;
        if (i < NE) {
            int d = edst[(size_t)r * NE + i];
            int s = esrc[(size_t)r * NE + i];
            int pos = g_rowptrF[r * NN + d] + atomicAdd(&g_fill[r * NN + d], 1);
            g_csrc[pos] = s;
            g_cdst[pos] = d;
        }
    } else {
        scores_block(x, vl0, vr0, (b - NR * FILLB) * 32);
    }
}

// =================== standalone scores (layers 1,2) ========================
__global__ void __launch_bounds__(256)
scores_kernel(const float* __restrict__ x,
              const float* __restrict__ vl,
              const float* __restrict__ vr) {
    scores_block(x, vl, vr, blockIdx.x * 32);
}

// =================== alpha: w = exp(leaky(el[s]+er[d])) per CSR slot =======
__global__ void __launch_bounds__(256)
alpha_kernel() {
    int i = blockIdx.x * 256 + threadIdx.x;
    if (i >= NR * NE) return;
    int r = i / NE;
    int s = g_csrc[i];
    int d = g_cdst[i];
    float v = g_el[(size_t)r * NN + s] + g_er[(size_t)r * NN + d];
    v = v > 0.f ? v : 0.2f * v;
    float w = expf(v);
    g_ws[i] = make_uint2(__float_as_uint(w), (unsigned)s);
}

// =================== aggregation: 2 rows per warp, 4-edge unroll ============
// Rows d0, d0+1 have contiguous CSR ranges -> sweep [rp[d0], rp[d0+2]) as one
// flat stream; branchless routing (wa/wb) into the two accumulator sets.
__device__ __forceinline__ uint32_t pack_bf2(__nv_bfloat16 a, __nv_bfloat16 b) {
    return (uint32_t)__bfloat16_as_ushort(a) |
           ((uint32_t)__bfloat16_as_ushort(b) << 16);
}

__device__ __forceinline__ void y_store(float ax, float ay, float az, float aw,
                                        float den, int r, int d, int lane) {
    float inv = den > 0.f ? 1.f / den : 0.f;
    ax *= inv; ay *= inv; az *= inv; aw *= inv;
    __nv_bfloat16 h0 = __float2bfloat16_rn(ax);
    __nv_bfloat16 h1 = __float2bfloat16_rn(ay);
    __nv_bfloat16 h2 = __float2bfloat16_rn(az);
    __nv_bfloat16 h3 = __float2bfloat16_rn(aw);
    __nv_bfloat16 l0 = __float2bfloat16_rn(ax - __bfloat162float(h0));
    __nv_bfloat16 l1 = __float2bfloat16_rn(ay - __bfloat162float(h1));
    __nv_bfloat16 l2 = __float2bfloat16_rn(az - __bfloat162float(h2));
    __nv_bfloat16 l3 = __float2bfloat16_rn(aw - __bfloat162float(h3));
    size_t off = ((size_t)r * NN + d) * DD + lane * 4;
    __stcs((uint2*)(g_yhi + off), make_uint2(pack_bf2(h0, h1), pack_bf2(h2, h3)));
    __stcs((uint2*)(g_ylo + off), make_uint2(pack_bf2(l0, l1), pack_bf2(l2, l3)));
}

__global__ void __launch_bounds__(256)
agg_kernel(const float* __restrict__ x) {
    int lane = threadIdx.x & 31;
    int pr = blockIdx.x * 8 + (threadIdx.x >> 5);   // row pair index
    int d0 = pr * 2;
    int r = blockIdx.y;
    if (d0 >= NN) return;

    const int* rp = g_rowptrF + (size_t)r * NN;
    const uint2* ws = g_ws;
    const float4* x4 = (const float4*)x;

    int st  = rp[d0];
    int mid = rp[d0 + 1];
    int en  = rp[d0 + 2];   // valid across boundaries (flattened, monotone)

    float a0x = 0.f, a0y = 0.f, a0z = 0.f, a0w = 0.f;
    float a1x = 0.f, a1y = 0.f, a1z = 0.f, a1w = 0.f;
    float den0 = 0.f, den1 = 0.f;

#define EDGE_ACC(P, V, EJ)                                                   \
    {                                                                        \
        float w_ = __uint_as_float((P).x);                                   \
        float wa = ((EJ) < mid) ? w_ : 0.f;                                  \
        float wb = w_ - wa;                                                  \
        den0 += wa; den1 += wb;                                              \
        a0x += wa * (V).x; a0y += wa * (V).y;                                \
        a0z += wa * (V).z; a0w += wa * (V).w;                                \
        a1x += wb * (V).x; a1y += wb * (V).y;                                \
        a1z += wb * (V).z; a1w += wb * (V).w;                                \
    }

    int e = st;
    for (; e + 4 <= en; e += 4) {
        uint2 p0 = ws[e];
        uint2 p1 = ws[e + 1];
        uint2 p2 = ws[e + 2];
        uint2 p3 = ws[e + 3];
        float4 v0 = x4[(size_t)(int)p0.y * 32 + lane];
        float4 v1 = x4[(size_t)(int)p1.y * 32 + lane];
        float4 v2 = x4[(size_t)(int)p2.y * 32 + lane];
        float4 v3 = x4[(size_t)(int)p3.y * 32 + lane];
        EDGE_ACC(p0, v0, e)
        EDGE_ACC(p1, v1, e + 1)
        EDGE_ACC(p2, v2, e + 2)
        EDGE_ACC(p3, v3, e + 3)
    }
    if (e + 2 <= en) {
        uint2 p0 = ws[e];
        uint2 p1 = ws[e + 1];
        float4 v0 = x4[(size_t)(int)p0.y * 32 + lane];
        float4 v1 = x4[(size_t)(int)p1.y * 32 + lane];
        EDGE_ACC(p0, v0, e)
        EDGE_ACC(p1, v1, e + 1)
        e += 2;
    }
    if (e < en) {
        uint2 p = ws[e];
        float4 v = x4[(size_t)(int)p.y * 32 + lane];
        EDGE_ACC(p, v, e)
    }
#undef EDGE_ACC

    y_store(a0x, a0y, a0z, a0w, den0, r, d0, lane);
    if (d0 + 1 < NN)
        y_store(a1x, a1y, a1z, a1w, den1, r, d0 + 1, lane);
}

// =================== HMMA GEMM (R11-proven, MTILE=64) ======================
#define PAD 136
#define MTILE 64

#define SA_HI 0
#define SA_LO (MTILE * PAD * 2)
#define SB_HI (2 * MTILE * PAD * 2)
#define SB_LO (SB_HI + 128 * PAD * 2)
#define SM_TOTAL (SB_LO + 128 * PAD * 2)   // 104448

__device__ __forceinline__ void mma_bf16(float* c, const uint32_t* a,
                                         const uint32_t* b) {
    asm volatile(
        "mma.sync.aligned.m16n8k16.row.col.f32.bf16.bf16.f32 "
        "{%0,%1,%2,%3}, {%4,%5,%6,%7}, {%8,%9}, {%0,%1,%2,%3};"
        : "+f"(c[0]), "+f"(c[1]), "+f"(c[2]), "+f"(c[3])
        : "r"(a[0]), "r"(a[1]), "r"(a[2]), "r"(a[3]), "r"(b[0]), "r"(b[1]));
}

__global__ void __launch_bounds__(256, 2)
gemm_agg_kernel(float* __restrict__ out, const float* __restrict__ bias,
                int relu,
                const __nv_bfloat16* __restrict__ whiL,
                const __nv_bfloat16* __restrict__ wloL) {
    extern __shared__ char smem[];
    __nv_bfloat16* Ahi = (__nv_bfloat16*)(smem + SA_HI);
    __nv_bfloat16* Alo = (__nv_bfloat16*)(smem + SA_LO);
    __nv_bfloat16* Bhi = (__nv_bfloat16*)(smem + SB_HI);
    __nv_bfloat16* Blo = (__nv_bfloat16*)(smem + SB_LO);

    int tid = threadIdx.x;
    int wid = tid >> 5;
    int lane = tid & 31;
    int m0 = blockIdx.x * MTILE;

    int wm = (wid >> 2) * 32;
    int wn = (wid & 3) * 32;
    int g4 = lane >> 2;
    int l4 = (lane & 3) * 2;

    float acc[2][4][4];
#pragma unroll
    for (int mt = 0; mt < 2; mt++)
#pragma unroll
        for (int nt = 0; nt < 4; nt++)
#pragma unroll
            for (int j = 0; j < 4; j++) acc[mt][nt][j] = 0.f;

    for (int r = 0; r < NR; r++) {
        __syncthreads();

        const uint4* whi4 = (const uint4*)(whiL + (size_t)r * DD * DD);
        const uint4* wlo4 = (const uint4*)(wloL + (size_t)r * DD * DD);
        const uint4* yhi4 = (const uint4*)g_yhi;
        const uint4* ylo4 = (const uint4*)g_ylo;
#pragma unroll
        for (int it = 0; it < 8; it++) {
            int idx = tid + it * 256;
            int row = idx >> 4, c8 = idx & 15;
            *(uint4*)(Bhi + row * PAD + c8 * 8) = whi4[idx];
            *(uint4*)(Blo + row * PAD + c8 * 8) = wlo4[idx];
        }
#pragma unroll
        for (int it = 0; it < 4; it++) {
            int idx = tid + it * 256;
            int row = idx >> 4, c8 = idx & 15;
            uint4 vhi = make_uint4(0, 0, 0, 0), vlo = make_uint4(0, 0, 0, 0);
            if (m0 + row < NN) {
                size_t gi = ((size_t)r * NN + m0 + row) * 16 + c8;
                vhi = __ldcs(&yhi4[gi]);
                vlo = __ldcs(&ylo4[gi]);
            }
            *(uint4*)(Ahi + row * PAD + c8 * 8) = vhi;
            *(uint4*)(Alo + row * PAD + c8 * 8) = vlo;
        }
        __syncthreads();

#pragma unroll
        for (int kk = 0; kk < 8; kk++) {
            int k = kk * 16;
            uint32_t ahi[2][4], alo[2][4];
#pragma unroll
            for (int mt = 0; mt < 2; mt++) {
                int r0 = wm + mt * 16 + g4;
                const __nv_bfloat16* ph = Ahi + r0 * PAD + k + l4;
                const __nv_bfloat16* pl = Alo + r0 * PAD + k + l4;
                ahi[mt][0] = *(const uint32_t*)(ph);
                ahi[mt][1] = *(const uint32_t*)(ph + 8 * PAD);
                ahi[mt][2] = *(const uint32_t*)(ph + 8);
                ahi[mt][3] = *(const uint32_t*)(ph + 8 * PAD + 8);
                alo[mt][0] = *(const uint32_t*)(pl);
                alo[mt][1] = *(const uint32_t*)(pl + 8 * PAD);
                alo[mt][2] = *(const uint32_t*)(pl + 8);
                alo[mt][3] = *(const uint32_t*)(pl + 8 * PAD + 8);
            }
            uint32_t bhi[4][2], blo[4][2];
#pragma unroll
            for (int nt = 0; nt < 4; nt++) {
                int n = wn + nt * 8 + g4;
                const __nv_bfloat16* ph = Bhi + n * PAD + k + l4;
                const __nv_bfloat16* pl = Blo + n * PAD + k + l4;
                bhi[nt][0] = *(const uint32_t*)(ph);
                bhi[nt][1] = *(const uint32_t*)(ph + 8);
                blo[nt][0] = *(const uint32_t*)(pl);
                blo[nt][1] = *(const uint32_t*)(pl + 8);
            }
#pragma unroll
            for (int mt = 0; mt < 2; mt++)
#pragma unroll
                for (int nt = 0; nt < 4; nt++) {
                    mma_bf16(acc[mt][nt], ahi[mt], bhi[nt]);
                    mma_bf16(acc[mt][nt], ahi[mt], blo[nt]);
                    mma_bf16(acc[mt][nt], alo[mt], bhi[nt]);
                }
        }
    }

#pragma unroll
    for (int mt = 0; mt < 2; mt++) {
        int row0 = m0 + wm + mt * 16 + g4;
        int row1 = row0 + 8;
#pragma unroll
        for (int nt = 0; nt < 4; nt++) {
            int col = wn + nt * 8 + l4;
            float b0 = bias[col], b1 = bias[col + 1];
            float v0 = acc[mt][nt][0] + b0, v1 = acc[mt][nt][1] + b1;
            float v2 = acc[mt][nt][2] + b0, v3 = acc[mt][nt][3] + b1;
            if (relu) {
                v0 = fmaxf(v0, 0.f); v1 = fmaxf(v1, 0.f);
                v2 = fmaxf(v2, 0.f); v3 = fmaxf(v3, 0.f);
            }
            if (row0 < NN)
                __stcs((float2*)(out + (size_t)row0 * DD + col),
                       make_float2(v0, v1));
            if (row1 < NN)
                __stcs((float2*)(out + (size_t)row1 * DD + col),
                       make_float2(v2, v3));
        }
    }
}

// ===========================================================================
extern "C" void kernel_launch(void* const* d_in, const int* in_sizes, int n_in,
                              void* d_out, int out_size) {
    const float* h    = (const float*)d_in[0];
    const int*   esrc = (const int*)d_in[1];
    const int*   edst = (const int*)d_in[2];
    const float* fsw  = (const float*)d_in[3];
    const float* fdw  = (const float*)d_in[4];
    const float* al   = (const float*)d_in[5];
    const float* ar   = (const float*)d_in[6];
    const float* hb   = (const float*)d_in[7];
    float* out_final  = (float*)d_out;

    float *bufA, *bufB, *vl, *vr;
    __nv_bfloat16 *whi, *wlo;
    cudaGetSymbolAddress((void**)&bufA, g_bufA);
    cudaGetSymbolAddress((void**)&bufB, g_bufB);
    cudaGetSymbolAddress((void**)&vl,   g_vl);
    cudaGetSymbolAddress((void**)&vr,   g_vr);
    cudaGetSymbolAddress((void**)&whi,  g_whi);
    cudaGetSymbolAddress((void**)&wlo,  g_wlo);

    cudaFuncSetAttribute(gemm_agg_kernel,
                         cudaFuncAttributeMaxDynamicSharedMemorySize, SM_TOTAL);

    const int MT = (NN + MTILE - 1) / MTILE;   // 1563
    const int AB = (NR * NE + 255) / 256;      // 12500
    const int PAIRS = (NN + 1) / 2;            // 50000
    const int AGB = (PAIRS + 7) / 8;           // 6250

    // 1: histogram (+ scan-state reset in tail blocks)
    hist_kernel<<<NR * FILLB + 7, 256>>>(edst);
    // 2: lookback scan + all-layer W prep + all-layer vecs
    scan_prep_kernel<<<SNB + 768 + 48, 512>>>(fsw, fdw, al, ar);
    // 3: CSR fill (+cdst) + layer-0 scores
    fill_scores_kernel<<<NR * FILLB + NN / 32, 256>>>(esrc, edst, h, vl, vr);

    const float* x = h;
    for (int l = 0; l < NL; l++) {
        float* out = (l == 0) ? bufB : (l == 1) ? bufA : out_final;

        if (l > 0)
            scores_kernel<<<NN / 32, 256>>>(x, vl + l * NR * DD,
                                            vr + l * NR * DD);
        alpha_kernel<<<AB, 256>>>();
        agg_kernel<<<dim3(AGB, NR), 256>>>(x);
        gemm_agg_kernel<<<MT, 256, SM_TOTAL>>>(out, hb + l * DD,
                                               l < NL - 1 ? 1 : 0,
                                               whi + (size_t)l * NR * DD * DD,
                                               wlo + (size_t)l * NR * DD * DD);
        x = out;
    }
}